// round 4
// baseline (speedup 1.0000x reference)
#include <cuda_runtime.h>

// ---------------------------------------------------------------------------
// AttentionLayer: context = softmax(Q K^T) V, scores = sum_q probs
//   Q = query @ Wq + bq   [pairs,256,1024]
//   K = source @ Wk + bk  [pairs,512,1024]
//   V = source @ Wv + bv  [pairs,512,1024]
// pairs = 8*32 = 256. All GEMMs in 3xTF32 (fp32-accurate) on mma.sync.
// R3: hi/lo pre-split into packed float2 smem (split out of inner loop),
//     XOR-swizzled conflict-free layout, double-buffered smem (1 sync/tile).
// ---------------------------------------------------------------------------

#define HID   1024
#define SEQQ  256
#define SEQK  512
#define PAIRS 256
#define MQ    (PAIRS * SEQQ)   // 65536
#define MS    (PAIRS * SEQK)   // 131072

// Scratch (allocation-free rule: __device__ globals)
__device__ float g_Q[(size_t)MQ * HID];
__device__ float g_K[(size_t)MS * HID];
__device__ float g_V[(size_t)MS * HID];
__device__ float g_S[(size_t)PAIRS * SEQQ * SEQK];

// smem tile geometry: [16 k][132 row/col] of float2{hi,lo}, double buffered
#define KSTRIDE 132
#define STAGE_F2 (16 * KSTRIDE)                 // float2 per array per stage
#define SMEM_BYTES (2 * 2 * STAGE_F2 * 8)       // 67584 B

// ---------------------------------------------------------------------------
// helpers
// ---------------------------------------------------------------------------
__device__ __forceinline__ float2 split2(float x) {
    unsigned h;
    asm("cvt.rna.tf32.f32 %0, %1;" : "=r"(h) : "f"(x));
    float2 r;
    r.x = __uint_as_float(h);
    r.y = x - r.x;
    return r;
}

__device__ __forceinline__ void mma_tf32(float c[4],
                                         unsigned a0, unsigned a1, unsigned a2, unsigned a3,
                                         unsigned b0, unsigned b1) {
    asm("mma.sync.aligned.m16n8k8.row.col.f32.tf32.tf32.f32 "
        "{%0,%1,%2,%3}, {%4,%5,%6,%7}, {%8,%9}, {%0,%1,%2,%3};"
        : "+f"(c[0]), "+f"(c[1]), "+f"(c[2]), "+f"(c[3])
        : "r"(a0), "r"(a1), "r"(a2), "r"(a3), "r"(b0), "r"(b1));
}

// ---------------------------------------------------------------------------
// Generic 3xTF32 GEMM: C[M,N] = A[M,K] * B + bias
//   TRANSB=false: B is [K,N] row-major.  TRANSB=true: B is [N,K] (C = A B^T).
// Block tile 128x128x16, 256 threads (2x4 warps, warp tile 64x32).
// ---------------------------------------------------------------------------
template <bool TRANSB, bool BIAS>
__global__ void __launch_bounds__(256, 1)
gemm3x(const float* __restrict__ A, const float* __restrict__ B,
       const float* __restrict__ bias, float* __restrict__ C,
       int K, int lda, int ldb, int ldc,
       size_t sA, size_t sB, size_t sC)
{
    extern __shared__ float2 sm[];
    float2* const As = sm;                     // [2][16][132]
    float2* const Bs = sm + 2 * STAGE_F2;      // [2][16][132]

    const int tid  = threadIdx.x;
    const int lane = tid & 31;
    const int wm   = (tid >> 5) >> 2;   // 0..1
    const int wn   = (tid >> 5) & 3;    // 0..3
    const int g    = lane >> 2;         // 0..7
    const int tg   = lane & 3;          // 0..3

    const size_t z = blockIdx.z;
    A += z * sA + (size_t)blockIdx.y * 128 * lda;
    if (TRANSB) B += z * sB + (size_t)blockIdx.x * 128 * ldb;
    else        B += z * sB + (size_t)blockIdx.x * 128;
    C += z * sC + (size_t)blockIdx.y * 128 * ldc + (size_t)blockIdx.x * 128;

    // global->reg load coordinates (two float4 each for A and B)
    const int aR0 = tid >> 2, aK0 = (tid & 3) * 4;   // A: 4 consecutive k
    const int aR1 = aR0 + 64;
    int bY0, bX0, bY1;
    if (TRANSB) { bY0 = tid >> 2;  bX0 = (tid & 3) * 4;  bY1 = bY0 + 64; } // n rows, k contiguous
    else        { bY0 = tid >> 5;  bX0 = (tid & 31) * 4; bY1 = bY0 + 8;  } // k rows, n contiguous

    float4 ra0, ra1, rb0, rb1;

    auto load_tile = [&](int t) {
        const float* At = A + (size_t)t * 16;
        ra0 = *(const float4*)(At + (size_t)aR0 * lda + aK0);
        ra1 = *(const float4*)(At + (size_t)aR1 * lda + aK0);
        if (TRANSB) {
            const float* Bt = B + (size_t)t * 16;
            rb0 = *(const float4*)(Bt + (size_t)bY0 * ldb + bX0);
            rb1 = *(const float4*)(Bt + (size_t)bY1 * ldb + bX0);
        } else {
            const float* Bt = B + (size_t)t * 16 * ldb;
            rb0 = *(const float4*)(Bt + (size_t)bY0 * ldb + bX0);
            rb1 = *(const float4*)(Bt + (size_t)bY1 * ldb + bX0);
        }
    };

    // stage: split f32 -> (tf32 hi, residual lo) and store packed float2.
    // A (and TRANSB B) are k-contiguous per thread: swizzle row ^ ((k>>2&3)<<2),
    // where k>>2 == tg for all 4 elements -> constant aswz.
    const int aswz = tg << 2;
    auto stage = [&](int s) {
        float2* A_ = As + s * STAGE_F2;
        float2* B_ = Bs + s * STAGE_F2;
        {
            const float* v = (const float*)&ra0;
            #pragma unroll
            for (int j = 0; j < 4; ++j)
                A_[(aK0 + j) * KSTRIDE + (aR0 ^ aswz)] = split2(v[j]);
            v = (const float*)&ra1;
            #pragma unroll
            for (int j = 0; j < 4; ++j)
                A_[(aK0 + j) * KSTRIDE + (aR1 ^ aswz)] = split2(v[j]);
        }
        if (TRANSB) {
            const float* v = (const float*)&rb0;
            #pragma unroll
            for (int j = 0; j < 4; ++j)
                B_[(bX0 + j) * KSTRIDE + (bY0 ^ aswz)] = split2(v[j]);
            v = (const float*)&rb1;
            #pragma unroll
            for (int j = 0; j < 4; ++j)
                B_[(bX0 + j) * KSTRIDE + (bY1 ^ aswz)] = split2(v[j]);
        } else {
            // n-contiguous per thread: swizzle n ^ ((n>>4)&3)
            const int c = (bX0 >> 4) & 3;
            const float* v = (const float*)&rb0;
            #pragma unroll
            for (int j = 0; j < 4; ++j)
                B_[bY0 * KSTRIDE + ((bX0 + j) ^ c)] = split2(v[j]);
            v = (const float*)&rb1;
            #pragma unroll
            for (int j = 0; j < 4; ++j)
                B_[bY1 * KSTRIDE + ((bX0 + j) ^ c)] = split2(v[j]);
        }
    };

    float acc[4][4][4];
    #pragma unroll
    for (int mi = 0; mi < 4; ++mi)
        #pragma unroll
        for (int ni = 0; ni < 4; ++ni)
            #pragma unroll
            for (int i = 0; i < 4; ++i) acc[mi][ni][i] = 0.f;

    const int nT = K >> 4;
    load_tile(0);
    stage(0);
    __syncthreads();

    for (int t = 0; t < nT; ++t) {
        if (t + 1 < nT) load_tile(t + 1);   // global loads in flight over compute

        const float2* A_ = As + (t & 1) * STAGE_F2;
        const float2* B_ = Bs + (t & 1) * STAGE_F2;

        #pragma unroll
        for (int kk = 0; kk < 2; ++kk) {
            const int k1 = kk * 8 + tg;
            const int k2 = k1 + 4;
            const int c1 = ((2 * kk) & 3) << 2;       // swizzle for k1 (k1>>2 == 2kk)
            const int c2 = ((2 * kk + 1) & 3) << 2;   // swizzle for k2

            float2 a[4][4];
            #pragma unroll
            for (int mi = 0; mi < 4; ++mi) {
                const int r = wm * 64 + mi * 16 + g;
                a[mi][0] = A_[k1 * KSTRIDE + (r ^ c1)];
                a[mi][1] = A_[k1 * KSTRIDE + ((r + 8) ^ c1)];
                a[mi][2] = A_[k2 * KSTRIDE + (r ^ c2)];
                a[mi][3] = A_[k2 * KSTRIDE + ((r + 8) ^ c2)];
            }
            float2 b[4][2];
            #pragma unroll
            for (int ni = 0; ni < 4; ++ni) {
                const int n = wn * 32 + ni * 8 + g;
                if (TRANSB) {
                    b[ni][0] = B_[k1 * KSTRIDE + (n ^ c1)];
                    b[ni][1] = B_[k2 * KSTRIDE + (n ^ c2)];
                } else {
                    const int c = (n >> 4) & 3;
                    b[ni][0] = B_[k1 * KSTRIDE + (n ^ c)];
                    b[ni][1] = B_[k2 * KSTRIDE + (n ^ c)];
                }
            }
            #pragma unroll
            for (int mi = 0; mi < 4; ++mi) {
                const unsigned ah0 = __float_as_uint(a[mi][0].x), ah1 = __float_as_uint(a[mi][1].x),
                               ah2 = __float_as_uint(a[mi][2].x), ah3 = __float_as_uint(a[mi][3].x);
                const unsigned al0 = __float_as_uint(a[mi][0].y), al1 = __float_as_uint(a[mi][1].y),
                               al2 = __float_as_uint(a[mi][2].y), al3 = __float_as_uint(a[mi][3].y);
                #pragma unroll
                for (int ni = 0; ni < 4; ++ni) {
                    const unsigned bh0 = __float_as_uint(b[ni][0].x), bh1 = __float_as_uint(b[ni][1].x);
                    const unsigned bl0 = __float_as_uint(b[ni][0].y), bl1 = __float_as_uint(b[ni][1].y);
                    mma_tf32(acc[mi][ni], ah0, ah1, ah2, ah3, bh0, bh1);
                    mma_tf32(acc[mi][ni], al0, al1, al2, al3, bh0, bh1);
                    mma_tf32(acc[mi][ni], ah0, ah1, ah2, ah3, bl0, bl1);
                }
            }
        }

        if (t + 1 < nT) {
            stage((t + 1) & 1);    // other buffer: no hazard with this tile's reads
            __syncthreads();       // single barrier per tile
        }
    }

    // epilogue
    const float* bptr = BIAS ? (bias + (size_t)blockIdx.x * 128) : bias;
    #pragma unroll
    for (int mi = 0; mi < 4; ++mi) {
        const int r = wm * 64 + mi * 16 + g;
        #pragma unroll
        for (int ni = 0; ni < 4; ++ni) {
            const int cn = wn * 32 + ni * 8 + tg * 2;
            float b0 = 0.f, b1 = 0.f;
            if (BIAS) { b0 = bptr[cn]; b1 = bptr[cn + 1]; }
            float2 v0 = make_float2(acc[mi][ni][0] + b0, acc[mi][ni][1] + b1);
            float2 v1 = make_float2(acc[mi][ni][2] + b0, acc[mi][ni][3] + b1);
            *(float2*)(C + (size_t)r * ldc + cn)       = v0;
            *(float2*)(C + (size_t)(r + 8) * ldc + cn) = v1;
        }
    }
}

// ---------------------------------------------------------------------------
// Softmax over rows of S [pairs,256,512] in place + column-sum into scores.
// ---------------------------------------------------------------------------
__global__ void __launch_bounds__(256)
softmax_scores(float* __restrict__ S, float* __restrict__ scores)
{
    const int pair = blockIdx.y;
    const int w    = threadIdx.x >> 5;
    const int lane = threadIdx.x & 31;

    __shared__ float colsum[SEQK];
    for (int i = threadIdx.x; i < SEQK; i += 256) colsum[i] = 0.f;
    __syncthreads();

    float* row = S + (size_t)pair * SEQQ * SEQK + (size_t)(blockIdx.x * 8 + w) * SEQK;

    float v[16];
    #pragma unroll
    for (int i = 0; i < 16; ++i) v[i] = row[lane + 32 * i];

    float m = v[0];
    #pragma unroll
    for (int i = 1; i < 16; ++i) m = fmaxf(m, v[i]);
    #pragma unroll
    for (int o = 16; o; o >>= 1) m = fmaxf(m, __shfl_xor_sync(0xffffffffu, m, o));

    float s = 0.f;
    #pragma unroll
    for (int i = 0; i < 16; ++i) { v[i] = __expf(v[i] - m); s += v[i]; }
    #pragma unroll
    for (int o = 16; o; o >>= 1) s += __shfl_xor_sync(0xffffffffu, s, o);

    const float inv = 1.f / s;
    #pragma unroll
    for (int i = 0; i < 16; ++i) {
        const float p = v[i] * inv;
        row[lane + 32 * i] = p;
        atomicAdd(&colsum[lane + 32 * i], p);
    }
    __syncthreads();
    for (int i = threadIdx.x; i < SEQK; i += 256)
        atomicAdd(&scores[(size_t)pair * SEQK + i], colsum[i]);
}

// ---------------------------------------------------------------------------
// kernel_launch
// inputs: query, source, Wq, bq, Wk, bk, Wv, bv
// output: context [8,32,256,1024] then attention_scores [8,32,512]
// ---------------------------------------------------------------------------
extern "C" void kernel_launch(void* const* d_in, const int* in_sizes, int n_in,
                              void* d_out, int out_size)
{
    const float* query  = (const float*)d_in[0];
    const float* source = (const float*)d_in[1];
    const float* Wq = (const float*)d_in[2];
    const float* bq = (const float*)d_in[3];
    const float* Wk = (const float*)d_in[4];
    const float* bk = (const float*)d_in[5];
    const float* Wv = (const float*)d_in[6];
    const float* bv = (const float*)d_in[7];

    float* ctx    = (float*)d_out;
    float* scores = ctx + (size_t)PAIRS * SEQQ * HID;

    float *Q, *Kb, *Vb, *S;
    cudaGetSymbolAddress((void**)&Q,  g_Q);
    cudaGetSymbolAddress((void**)&Kb, g_K);
    cudaGetSymbolAddress((void**)&Vb, g_V);
    cudaGetSymbolAddress((void**)&S,  g_S);

    // opt-in to >48KB dynamic smem (idempotent; not a stream op, capture-safe)
    cudaFuncSetAttribute(gemm3x<false, true>,  cudaFuncAttributeMaxDynamicSharedMemorySize, SMEM_BYTES);
    cudaFuncSetAttribute(gemm3x<true,  false>, cudaFuncAttributeMaxDynamicSharedMemorySize, SMEM_BYTES);
    cudaFuncSetAttribute(gemm3x<false, false>, cudaFuncAttributeMaxDynamicSharedMemorySize, SMEM_BYTES);

    cudaMemsetAsync(scores, 0, (size_t)PAIRS * SEQK * sizeof(float));

    dim3 blk(256);
    // projections (N = K = 1024)
    gemm3x<false, true><<<dim3(HID / 128, MQ / 128, 1), blk, SMEM_BYTES>>>(
        query, Wq, bq, Q, HID, HID, HID, HID, 0, 0, 0);
    gemm3x<false, true><<<dim3(HID / 128, MS / 128, 1), blk, SMEM_BYTES>>>(
        source, Wk, bk, Kb, HID, HID, HID, HID, 0, 0, 0);
    gemm3x<false, true><<<dim3(HID / 128, MS / 128, 1), blk, SMEM_BYTES>>>(
        source, Wv, bv, Vb, HID, HID, HID, HID, 0, 0, 0);
    // logits S = Q K^T (batched over pairs)
    gemm3x<true, false><<<dim3(SEQK / 128, SEQQ / 128, PAIRS), blk, SMEM_BYTES>>>(
        Q, Kb, nullptr, S, HID, HID, HID, SEQK,
        (size_t)SEQQ * HID, (size_t)SEQK * HID, (size_t)SEQQ * SEQK);
    // softmax + scores
    softmax_scores<<<dim3(SEQQ / 8, PAIRS), 256>>>(S, scores);
    // context = P V (batched)
    gemm3x<false, false><<<dim3(HID / 128, SEQQ / 128, PAIRS), blk, SMEM_BYTES>>>(
        S, Vb, nullptr, ctx, SEQK, SEQK, HID, HID,
        (size_t)SEQQ * SEQK, (size_t)SEQK * HID, (size_t)SEQQ * HID);
}

// round 5
// speedup vs baseline: 1.1539x; 1.1539x over previous
#include <cuda_runtime.h>

// ---------------------------------------------------------------------------
// AttentionLayer: context = softmax(Q K^T) V, scores = sum_q probs
//   Q = query @ Wq + bq   [pairs,256,1024]
//   K = source @ Wk + bk  [pairs,512,1024]
//   V = source @ Wv + bv  [pairs,512,1024]
// pairs = 256. 3xTF32 on mma.sync; R4: fragment-ready pre-split float4 smem
// (hi/lo pairs, one LDS.128 per fragment, immediate-foldable addressing),
// 2 CTAs/SM.
// ---------------------------------------------------------------------------

#define HID   1024
#define SEQQ  256
#define SEQK  512
#define PAIRS 256
#define MQ    (PAIRS * SEQQ)   // 65536
#define MS    (PAIRS * SEQK)   // 131072

// Scratch (allocation-free rule: __device__ globals)
__device__ float g_Q[(size_t)MQ * HID];
__device__ float g_K[(size_t)MS * HID];
__device__ float g_V[(size_t)MS * HID];
__device__ float g_S[(size_t)PAIRS * SEQQ * SEQK];

// pre-split tile: 128 rows x 8 k-pair slots (float4 {hi_k, hi_k4, lo_k, lo_k4}),
// row stride 9 float4 (pad) -> conflict-free LDS.128 fragments.
#define AS4 9
#define A4_ELEMS (128 * AS4)               // float4 per tile
#define SMEM_TRANS  (2 * A4_ELEMS * 16)    // A4 + B4            = 36864 B
#define SMEM_NTRANS (A4_ELEMS * 16 + 16 * 136 * 4)  //          = 27136 B

// ---------------------------------------------------------------------------
__device__ __forceinline__ float2 split2(float x) {
    unsigned h;
    asm("cvt.rna.tf32.f32 %0, %1;" : "=r"(h) : "f"(x));
    float2 r;
    r.x = __uint_as_float(h);
    r.y = x - r.x;
    return r;
}

__device__ __forceinline__ void mma_tf32(float c[4],
                                         float a0, float a1, float a2, float a3,
                                         float b0, float b1) {
    asm("mma.sync.aligned.m16n8k8.row.col.f32.tf32.tf32.f32 "
        "{%0,%1,%2,%3}, {%4,%5,%6,%7}, {%8,%9}, {%0,%1,%2,%3};"
        : "+f"(c[0]), "+f"(c[1]), "+f"(c[2]), "+f"(c[3])
        : "r"(__float_as_uint(a0)), "r"(__float_as_uint(a1)),
          "r"(__float_as_uint(a2)), "r"(__float_as_uint(a3)),
          "r"(__float_as_uint(b0)), "r"(__float_as_uint(b1)));
}

// ---------------------------------------------------------------------------
// Generic 3xTF32 GEMM: C[M,N] = A[M,K] * B + bias
//   TRANSB=false: B is [K,N] row-major.  TRANSB=true: B is [N,K] (C = A B^T).
// Block tile 128x128x16, 256 threads (2x4 warps, warp tile 64x32), 2 CTA/SM.
// ---------------------------------------------------------------------------
template <bool TRANSB, bool BIAS>
__global__ void __launch_bounds__(256, 2)
gemm3x(const float* __restrict__ A, const float* __restrict__ B,
       const float* __restrict__ bias, float* __restrict__ C,
       int K, int lda, int ldb, int ldc,
       size_t sA, size_t sB, size_t sC)
{
    extern __shared__ float4 sm4[];
    float4* const A4 = sm4;                         // [128][AS4] pre-split A
    float4* const B4 = sm4 + A4_ELEMS;              // TRANSB: pre-split B
    float* const Bs  = (float*)(sm4 + A4_ELEMS);    // !TRANSB: [16][136] raw B

    const int tid  = threadIdx.x;
    const int lane = tid & 31;
    const int wm   = (tid >> 5) >> 2;   // 0..1
    const int wn   = (tid >> 5) & 3;    // 0..3
    const int g    = lane >> 2;         // 0..7
    const int tg   = lane & 3;          // 0..3

    const size_t z = blockIdx.z;
    A += z * sA + (size_t)blockIdx.y * 128 * lda;
    if (TRANSB) B += z * sB + (size_t)blockIdx.x * 128 * ldb;
    else        B += z * sB + (size_t)blockIdx.x * 128;
    C += z * sC + (size_t)blockIdx.y * 128 * ldc + (size_t)blockIdx.x * 128;

    // global load coords: A rows (k-contiguous), 4 consecutive k per thread
    const int aR0 = tid >> 2, aK0 = (tid & 3) * 4;
    const int aR1 = aR0 + 64;
    const int kkA = aK0 >> 3;            // slot low bit
    const int hfA = (aK0 >> 2) & 1;      // component half
    int bY0, bX0, bY1;
    if (TRANSB) { bY0 = tid >> 2;  bX0 = (tid & 3) * 4;  bY1 = bY0 + 64; }
    else        { bY0 = tid >> 5;  bX0 = (tid & 31) * 4; bY1 = bY0 + 8;  }
    const int kkB = bX0 >> 3, hfB = (bX0 >> 2) & 1;   // TRANSB only

    float4 ra0, ra1, rb0, rb1;

    auto load_tile = [&](int t) {
        const float* At = A + (size_t)t * 16;
        ra0 = *(const float4*)(At + (size_t)aR0 * lda + aK0);
        ra1 = *(const float4*)(At + (size_t)aR1 * lda + aK0);
        if (TRANSB) {
            const float* Bt = B + (size_t)t * 16;
            rb0 = *(const float4*)(Bt + (size_t)bY0 * ldb + bX0);
            rb1 = *(const float4*)(Bt + (size_t)bY1 * ldb + bX0);
        } else {
            const float* Bt = B + (size_t)t * 16 * ldb;
            rb0 = *(const float4*)(Bt + (size_t)bY0 * ldb + bX0);
            rb1 = *(const float4*)(Bt + (size_t)bY1 * ldb + bX0);
        }
    };

    // pre-split staging: element k -> slot p = 2*(k&3) + (k>>3),
    // component: [hf] = hi, [2+hf] = lo (hf = (k>>2)&1).
    auto stage = [&]() {
        {
            const float* v = (const float*)&ra0;
            #pragma unroll
            for (int j = 0; j < 4; ++j) {
                float2 s = split2(v[j]);
                float* slot = (float*)&A4[aR0 * AS4 + 2 * j + kkA];
                slot[hfA] = s.x; slot[2 + hfA] = s.y;
            }
            v = (const float*)&ra1;
            #pragma unroll
            for (int j = 0; j < 4; ++j) {
                float2 s = split2(v[j]);
                float* slot = (float*)&A4[aR1 * AS4 + 2 * j + kkA];
                slot[hfA] = s.x; slot[2 + hfA] = s.y;
            }
        }
        if (TRANSB) {
            const float* v = (const float*)&rb0;
            #pragma unroll
            for (int j = 0; j < 4; ++j) {
                float2 s = split2(v[j]);
                float* slot = (float*)&B4[bY0 * AS4 + 2 * j + kkB];
                slot[hfB] = s.x; slot[2 + hfB] = s.y;
            }
            v = (const float*)&rb1;
            #pragma unroll
            for (int j = 0; j < 4; ++j) {
                float2 s = split2(v[j]);
                float* slot = (float*)&B4[bY1 * AS4 + 2 * j + kkB];
                slot[hfB] = s.x; slot[2 + hfB] = s.y;
            }
        } else {
            *(float4*)&Bs[bY0 * 136 + bX0] = rb0;
            *(float4*)&Bs[bY1 * 136 + bX0] = rb1;
        }
    };

    float acc[4][4][4];
    #pragma unroll
    for (int mi = 0; mi < 4; ++mi)
        #pragma unroll
        for (int ni = 0; ni < 4; ++ni)
            #pragma unroll
            for (int i = 0; i < 4; ++i) acc[mi][ni][i] = 0.f;

    const int nT = K >> 4;
    load_tile(0);
    stage();
    __syncthreads();

    for (int t = 0; t < nT; ++t) {
        if (t + 1 < nT) load_tile(t + 1);   // LDGs in flight over compute

        #pragma unroll
        for (int kk = 0; kk < 2; ++kk) {
            const int p = 2 * tg + kk;      // slot: per-thread const + imm

            // A fragments: one LDS.128 per row-half, fully immediate-addressed
            float4 fL[4], fH[4];
            #pragma unroll
            for (int mi = 0; mi < 4; ++mi) {
                const int r = wm * 64 + mi * 16 + g;
                fL[mi] = A4[r * AS4 + p];
                fH[mi] = A4[(r + 8) * AS4 + p];
            }

            #pragma unroll
            for (int ni = 0; ni < 4; ++ni) {
                const int n = wn * 32 + ni * 8 + g;
                float bh0, bh1, bl0, bl1;
                if (TRANSB) {
                    float4 gb = B4[n * AS4 + p];
                    bh0 = gb.x; bh1 = gb.y; bl0 = gb.z; bl1 = gb.w;
                } else {
                    const int k1 = kk * 8 + tg;
                    float2 s0 = split2(Bs[k1 * 136 + n]);
                    float2 s1 = split2(Bs[(k1 + 4) * 136 + n]);
                    bh0 = s0.x; bh1 = s1.x; bl0 = s0.y; bl1 = s1.y;
                }
                #pragma unroll
                for (int mi = 0; mi < 4; ++mi) {
                    mma_tf32(acc[mi][ni], fL[mi].x, fH[mi].x, fL[mi].y, fH[mi].y, bh0, bh1);
                    mma_tf32(acc[mi][ni], fL[mi].z, fH[mi].z, fL[mi].w, fH[mi].w, bh0, bh1);
                    mma_tf32(acc[mi][ni], fL[mi].x, fH[mi].x, fL[mi].y, fH[mi].y, bl0, bl1);
                }
            }
        }

        if (t + 1 < nT) {
            __syncthreads();
            stage();
            __syncthreads();
        }
    }

    // epilogue
    const float* bptr = BIAS ? (bias + (size_t)blockIdx.x * 128) : bias;
    #pragma unroll
    for (int mi = 0; mi < 4; ++mi) {
        const int r = wm * 64 + mi * 16 + g;
        #pragma unroll
        for (int ni = 0; ni < 4; ++ni) {
            const int cn = wn * 32 + ni * 8 + tg * 2;
            float b0 = 0.f, b1 = 0.f;
            if (BIAS) { b0 = bptr[cn]; b1 = bptr[cn + 1]; }
            float2 v0 = make_float2(acc[mi][ni][0] + b0, acc[mi][ni][1] + b1);
            float2 v1 = make_float2(acc[mi][ni][2] + b0, acc[mi][ni][3] + b1);
            *(float2*)(C + (size_t)r * ldc + cn)       = v0;
            *(float2*)(C + (size_t)(r + 8) * ldc + cn) = v1;
        }
    }
}

// ---------------------------------------------------------------------------
// Softmax over rows of S [pairs,256,512] in place + column-sum into scores.
// ---------------------------------------------------------------------------
__global__ void __launch_bounds__(256)
softmax_scores(float* __restrict__ S, float* __restrict__ scores)
{
    const int pair = blockIdx.y;
    const int w    = threadIdx.x >> 5;
    const int lane = threadIdx.x & 31;

    __shared__ float colsum[SEQK];
    for (int i = threadIdx.x; i < SEQK; i += 256) colsum[i] = 0.f;
    __syncthreads();

    float* row = S + (size_t)pair * SEQQ * SEQK + (size_t)(blockIdx.x * 8 + w) * SEQK;

    float v[16];
    #pragma unroll
    for (int i = 0; i < 16; ++i) v[i] = row[lane + 32 * i];

    float m = v[0];
    #pragma unroll
    for (int i = 1; i < 16; ++i) m = fmaxf(m, v[i]);
    #pragma unroll
    for (int o = 16; o; o >>= 1) m = fmaxf(m, __shfl_xor_sync(0xffffffffu, m, o));

    float s = 0.f;
    #pragma unroll
    for (int i = 0; i < 16; ++i) { v[i] = __expf(v[i] - m); s += v[i]; }
    #pragma unroll
    for (int o = 16; o; o >>= 1) s += __shfl_xor_sync(0xffffffffu, s, o);

    const float inv = 1.f / s;
    #pragma unroll
    for (int i = 0; i < 16; ++i) {
        const float p = v[i] * inv;
        row[lane + 32 * i] = p;
        atomicAdd(&colsum[lane + 32 * i], p);
    }
    __syncthreads();
    for (int i = threadIdx.x; i < SEQK; i += 256)
        atomicAdd(&scores[(size_t)pair * SEQK + i], colsum[i]);
}

// ---------------------------------------------------------------------------
// kernel_launch
// inputs: query, source, Wq, bq, Wk, bk, Wv, bv
// output: context [8,32,256,1024] then attention_scores [8,32,512]
// ---------------------------------------------------------------------------
extern "C" void kernel_launch(void* const* d_in, const int* in_sizes, int n_in,
                              void* d_out, int out_size)
{
    const float* query  = (const float*)d_in[0];
    const float* source = (const float*)d_in[1];
    const float* Wq = (const float*)d_in[2];
    const float* bq = (const float*)d_in[3];
    const float* Wk = (const float*)d_in[4];
    const float* bk = (const float*)d_in[5];
    const float* Wv = (const float*)d_in[6];
    const float* bv = (const float*)d_in[7];

    float* ctx    = (float*)d_out;
    float* scores = ctx + (size_t)PAIRS * SEQQ * HID;

    float *Q, *Kb, *Vb, *S;
    cudaGetSymbolAddress((void**)&Q,  g_Q);
    cudaGetSymbolAddress((void**)&Kb, g_K);
    cudaGetSymbolAddress((void**)&Vb, g_V);
    cudaGetSymbolAddress((void**)&S,  g_S);

    cudaMemsetAsync(scores, 0, (size_t)PAIRS * SEQK * sizeof(float));

    dim3 blk(256);
    // projections (N = K = 1024)
    gemm3x<false, true><<<dim3(HID / 128, MQ / 128, 1), blk, SMEM_NTRANS>>>(
        query, Wq, bq, Q, HID, HID, HID, HID, 0, 0, 0);
    gemm3x<false, true><<<dim3(HID / 128, MS / 128, 1), blk, SMEM_NTRANS>>>(
        source, Wk, bk, Kb, HID, HID, HID, HID, 0, 0, 0);
    gemm3x<false, true><<<dim3(HID / 128, MS / 128, 1), blk, SMEM_NTRANS>>>(
        source, Wv, bv, Vb, HID, HID, HID, HID, 0, 0, 0);
    // logits S = Q K^T (batched over pairs)
    gemm3x<true, false><<<dim3(SEQK / 128, SEQQ / 128, PAIRS), blk, SMEM_TRANS>>>(
        Q, Kb, nullptr, S, HID, HID, HID, SEQK,
        (size_t)SEQQ * HID, (size_t)SEQK * HID, (size_t)SEQQ * SEQK);
    // softmax + scores
    softmax_scores<<<dim3(SEQQ / 8, PAIRS), 256>>>(S, scores);
    // context = P V (batched)
    gemm3x<false, false><<<dim3(HID / 128, SEQQ / 128, PAIRS), blk, SMEM_NTRANS>>>(
        S, Vb, nullptr, ctx, SEQK, SEQK, HID, HID,
        (size_t)SEQQ * SEQK, (size_t)SEQK * HID, (size_t)SEQQ * HID);
}